// round 1
// baseline (speedup 1.0000x reference)
#include <cuda_runtime.h>
#include <math.h>

// WaveNet_39118562132426 — fp32 baseline, fused per-layer kernels.
// h buffers ping-pong in device globals (stay L2-resident), skip accumulates
// in a device global. 22 launches total.

#define HS 65536            // h row stride (time)
#define TT 128              // time tile
#define TOUT 63489          // T - 2048 + 1
#define NLAYER 20

__device__ float g_h[2][64 * HS];     // 2 x 16 MB
__device__ float g_skip[64 * TOUT];   // 16.2 MB

// ---------------------------------------------------------------------------
__global__ void init_kernel(const float* __restrict__ input,
                            const float* __restrict__ w0,
                            const float* __restrict__ b0) {
    int stride = gridDim.x * blockDim.x;
    for (int idx = blockIdx.x * blockDim.x + threadIdx.x; idx < 64 * HS; idx += stride) {
        int c = idx >> 16;
        int t = idx & (HS - 1);
        g_h[0][idx] = w0[c] * input[t] + b0[c];  // idx == c*HS + t
    }
    for (int idx = blockIdx.x * blockDim.x + threadIdx.x; idx < 64 * TOUT; idx += stride) {
        g_skip[idx] = 0.0f;
    }
}

// ---------------------------------------------------------------------------
// One dilated layer:
//   pre[128,t] = W1[128,128] @ [h(:,t); h(:,t+d)]    (rows 0..63 = f, 64..127 = g)
//   z = tanh(f+bf) * sigmoid(g+bg)
//   [res;skip][128,t] = W2[128,64] @ z
//   h_out = res + br + h(:,t+d);  skip accum at col t - skip_shift
// smem: sW1 [128][128] | sX [128][TT] (reused as act) | sW2 [64][128]
__global__ void __launch_bounds__(512, 1) layer_kernel(
    const float* __restrict__ wf, const float* __restrict__ wg,
    const float* __restrict__ wr, const float* __restrict__ ws,
    const float* __restrict__ bf, const float* __restrict__ bg,
    const float* __restrict__ br, const float* __restrict__ bs,
    int inbuf, int W, int d, int skip_shift)
{
    extern __shared__ float smem[];
    float* sW1 = smem;                       // 128*128
    float* sX  = smem + 128 * 128;           // 128*TT
    float* sW2 = smem + 128 * 128 + 128 * TT; // 64*128

    const float* __restrict__ hin = g_h[inbuf];
    float* __restrict__ hout = g_h[1 - inbuf];
    const int tid = threadIdx.x;

    // Load weights once per CTA (persistent grid).
    for (int idx = tid; idx < 128 * 128; idx += 512) {
        int k = idx >> 7, m = idx & 127;
        int c = k & 63, lr = k >> 6;
        float v = (m < 64) ? wf[(m * 64 + c) * 2 + lr]
                           : wg[((m - 64) * 64 + c) * 2 + lr];
        sW1[k * 128 + m] = v;
    }
    for (int idx = tid; idx < 64 * 128; idx += 512) {
        int k = idx >> 7, m = idx & 127;
        float v = (m < 64) ? wr[m * 64 + k] : ws[(m - 64) * 64 + k];
        sW2[k * 128 + m] = v;
    }
    __syncthreads();

    const int Wout = W - d;
    const int ntiles = (Wout + TT - 1) / TT;
    const int tg = tid & 31;    // 32 groups x 4 t
    const int mg = tid >> 5;    // 16 groups x 8 m
    const int tb = tg * 4;
    const int mb = mg * 8;

    for (int tile = blockIdx.x; tile < ntiles; tile += gridDim.x) {
        const int t0 = tile * TT;
        const bool full = (t0 + TT <= Wout);

        // Stage X = [left; right] into smem.
        if (full) {
            for (int idx = tid; idx < 64 * (TT / 4); idx += 512) {
                int k = idx >> 5;
                int t4 = (idx & 31) << 2;
                *(float4*)&sX[k * TT + t4] =
                    *(const float4*)&hin[k * HS + t0 + t4];
            }
            for (int idx = tid; idx < 64 * TT; idx += 512) {
                int k = idx >> 7, t = idx & 127;
                sX[(64 + k) * TT + t] = hin[k * HS + t0 + t + d];
            }
        } else {
            for (int idx = tid; idx < 128 * TT; idx += 512) {
                int k = idx >> 7, t = idx & 127;
                int c = k & 63;
                int lt = t0 + t;
                float v = 0.0f;
                if (lt < Wout) v = hin[c * HS + lt + ((k >= 64) ? d : 0)];
                sX[k * TT + t] = v;
            }
        }
        __syncthreads();

        // GEMM1: 128 x TT x K=128
        float acc[8][4];
        #pragma unroll
        for (int i = 0; i < 8; i++)
            #pragma unroll
            for (int j = 0; j < 4; j++) acc[i][j] = 0.0f;

        #pragma unroll 8
        for (int k = 0; k < 128; k++) {
            float a[8], b[4];
            *(float4*)&a[0] = *(const float4*)&sW1[k * 128 + mb];
            *(float4*)&a[4] = *(const float4*)&sW1[k * 128 + mb + 4];
            *(float4*)&b[0] = *(const float4*)&sX[k * TT + tb];
            #pragma unroll
            for (int i = 0; i < 8; i++)
                #pragma unroll
                for (int j = 0; j < 4; j++)
                    acc[i][j] += a[i] * b[j];
        }
        __syncthreads();  // all reads of sX done; safe to overwrite

        // Activations -> sX (reused): rows 0..63 tanh(f), 64..127 sigmoid(g)
        #pragma unroll
        for (int i = 0; i < 8; i++) {
            int m = mb + i;
            float bias = (m < 64) ? bf[m] : bg[m - 64];
            #pragma unroll
            for (int j = 0; j < 4; j++) {
                float v = acc[i][j] + bias;
                v = (m < 64) ? tanhf(v) : (1.0f / (1.0f + expf(-v)));
                sX[m * TT + tb + j] = v;
            }
        }
        __syncthreads();

        // z = f_act * g_act, into lower half of sX
        for (int idx = tid; idx < 64 * TT; idx += 512) {
            sX[idx] = sX[idx] * sX[64 * TT + idx];
        }
        __syncthreads();

        // GEMM2: 128 x TT x K=64  (rows 0..63 = res, 64..127 = skip)
        float acc2[8][4];
        #pragma unroll
        for (int i = 0; i < 8; i++)
            #pragma unroll
            for (int j = 0; j < 4; j++) acc2[i][j] = 0.0f;

        #pragma unroll 8
        for (int k = 0; k < 64; k++) {
            float a[8], b[4];
            *(float4*)&a[0] = *(const float4*)&sW2[k * 128 + mb];
            *(float4*)&a[4] = *(const float4*)&sW2[k * 128 + mb + 4];
            *(float4*)&b[0] = *(const float4*)&sX[k * TT + tb];
            #pragma unroll
            for (int i = 0; i < 8; i++)
                #pragma unroll
                for (int j = 0; j < 4; j++)
                    acc2[i][j] += a[i] * b[j];
        }

        // Epilogue
        if (mb < 64) {
            #pragma unroll
            for (int i = 0; i < 8; i++) {
                int m = mb + i;
                float bias = br[m];
                #pragma unroll
                for (int j = 0; j < 4; j++) {
                    int gt = t0 + tb + j;
                    if (gt < Wout)
                        hout[m * HS + gt] = acc2[i][j] + bias + hin[m * HS + gt + d];
                }
            }
        } else {
            #pragma unroll
            for (int i = 0; i < 8; i++) {
                int s = mb - 64 + i;
                float bias = bs[s];
                #pragma unroll
                for (int j = 0; j < 4; j++) {
                    int gt = t0 + tb + j;
                    int gc = gt - skip_shift;
                    if (gt < Wout && gc >= 0 && gc < TOUT)
                        g_skip[s * TOUT + gc] += acc2[i][j] + bias;
                }
            }
        }
        __syncthreads();
    }
}

// ---------------------------------------------------------------------------
// Output head: lrelu(alpha0) -> w_out0 (+b) -> lrelu(alpha1) -> w_out1 (+b)
// smem: sW0 [64][64] | sW1o [64][256] | sA [64][128] | sB [64][128]
__global__ void __launch_bounds__(512, 1) final_kernel(
    const float* __restrict__ alpha,
    const float* __restrict__ w_out0, const float* __restrict__ b_out0,
    const float* __restrict__ w_out1, const float* __restrict__ b_out1,
    float* __restrict__ out)
{
    extern __shared__ float smem[];
    float* sW0  = smem;               // 64*64
    float* sW1o = sW0 + 64 * 64;      // 64*256
    float* sA   = sW1o + 64 * 256;    // 64*128
    float* sB   = sA + 64 * 128;      // 64*128
    const int tid = threadIdx.x;

    for (int idx = tid; idx < 64 * 64; idx += 512) {
        int k = idx >> 6, m = idx & 63;
        sW0[k * 64 + m] = w_out0[m * 64 + k];
    }
    for (int idx = tid; idx < 64 * 256; idx += 512) {
        int k = idx >> 8, m = idx & 255;
        sW1o[k * 256 + m] = w_out1[m * 64 + k];
    }
    __syncthreads();

    const int ntiles = (TOUT + 127) / 128;
    const int tg = tid & 31;   // 32 x 4t
    const int mg = tid >> 5;   // 16 groups

    for (int tile = blockIdx.x; tile < ntiles; tile += gridDim.x) {
        const int t0 = tile * 128;

        for (int idx = tid; idx < 64 * 128; idx += 512) {
            int c = idx >> 7, t = idx & 127;
            int gt = t0 + t;
            float v = (gt < TOUT) ? g_skip[c * TOUT + gt] : 0.0f;
            v = (v > 0.0f) ? v : alpha[c] * v;
            sA[c * 128 + t] = v;
        }
        __syncthreads();

        // GEMM0: 64 x 128, K=64; thread tile 4m x 4t
        {
            float acc[4][4];
            #pragma unroll
            for (int i = 0; i < 4; i++)
                #pragma unroll
                for (int j = 0; j < 4; j++) acc[i][j] = 0.0f;
            int mb = mg * 4;
            #pragma unroll 8
            for (int k = 0; k < 64; k++) {
                float a[4], b[4];
                *(float4*)&a[0] = *(const float4*)&sW0[k * 64 + mb];
                *(float4*)&b[0] = *(const float4*)&sA[k * 128 + tg * 4];
                #pragma unroll
                for (int i = 0; i < 4; i++)
                    #pragma unroll
                    for (int j = 0; j < 4; j++)
                        acc[i][j] += a[i] * b[j];
            }
            #pragma unroll
            for (int i = 0; i < 4; i++) {
                int m = mb + i;
                float bias = b_out0[m];
                float al = alpha[64 + m];
                #pragma unroll
                for (int j = 0; j < 4; j++) {
                    float v = acc[i][j] + bias;
                    v = (v > 0.0f) ? v : al * v;
                    sB[m * 128 + tg * 4 + j] = v;
                }
            }
        }
        __syncthreads();

        // GEMM1: 256 x 128, K=64; thread tile 16m x 4t
        {
            float acc[16][4];
            #pragma unroll
            for (int i = 0; i < 16; i++)
                #pragma unroll
                for (int j = 0; j < 4; j++) acc[i][j] = 0.0f;
            int mb = mg * 16;
            #pragma unroll 4
            for (int k = 0; k < 64; k++) {
                float a[16], b[4];
                *(float4*)&a[0]  = *(const float4*)&sW1o[k * 256 + mb];
                *(float4*)&a[4]  = *(const float4*)&sW1o[k * 256 + mb + 4];
                *(float4*)&a[8]  = *(const float4*)&sW1o[k * 256 + mb + 8];
                *(float4*)&a[12] = *(const float4*)&sW1o[k * 256 + mb + 12];
                *(float4*)&b[0]  = *(const float4*)&sB[k * 128 + tg * 4];
                #pragma unroll
                for (int i = 0; i < 16; i++)
                    #pragma unroll
                    for (int j = 0; j < 4; j++)
                        acc[i][j] += a[i] * b[j];
            }
            #pragma unroll
            for (int i = 0; i < 16; i++) {
                int m = mb + i;
                float bias = b_out1[m];
                #pragma unroll
                for (int j = 0; j < 4; j++) {
                    int gt = t0 + tg * 4 + j;
                    if (gt < TOUT) out[m * TOUT + gt] = acc[i][j] + bias;
                }
            }
        }
        __syncthreads();
    }
}

// ---------------------------------------------------------------------------
extern "C" void kernel_launch(void* const* d_in, const int* in_sizes, int n_in,
                              void* d_out, int out_size) {
    const float* input  = (const float*)d_in[0];
    const float* w0     = (const float*)d_in[1];
    const float* b0     = (const float*)d_in[2];
    const float* wf     = (const float*)d_in[3];
    const float* bf     = (const float*)d_in[4];
    const float* wg     = (const float*)d_in[5];
    const float* bg     = (const float*)d_in[6];
    const float* wr     = (const float*)d_in[7];
    const float* br     = (const float*)d_in[8];
    const float* ws     = (const float*)d_in[9];
    const float* bs     = (const float*)d_in[10];
    const float* alpha  = (const float*)d_in[11];
    const float* w_out0 = (const float*)d_in[12];
    const float* b_out0 = (const float*)d_in[13];
    const float* w_out1 = (const float*)d_in[14];
    const float* b_out1 = (const float*)d_in[15];

    const int SMEM_LAYER = (128 * 128 + 128 * TT + 64 * 128) * 4;       // 160 KB
    const int SMEM_FINAL = (64 * 64 + 64 * 256 + 2 * 64 * 128) * 4;     // 144 KB
    cudaFuncSetAttribute(layer_kernel, cudaFuncAttributeMaxDynamicSharedMemorySize, SMEM_LAYER);
    cudaFuncSetAttribute(final_kernel, cudaFuncAttributeMaxDynamicSharedMemorySize, SMEM_FINAL);

    init_kernel<<<512, 256>>>(input, w0, b0);

    int W = HS;
    int offset = 2048;
    int buf = 0;
    for (int i = 0; i < NLAYER; i++) {
        int d = 1 << (i % 10);
        offset -= d;
        layer_kernel<<<148, 512, SMEM_LAYER>>>(
            wf + i * 64 * 64 * 2, wg + i * 64 * 64 * 2,
            wr + i * 64 * 64,     ws + i * 64 * 64,
            bf + i * 64, bg + i * 64, br + i * 64, bs + i * 64,
            buf, W, d, offset - 1);
        W -= d;
        buf ^= 1;
    }

    final_kernel<<<148, 512, SMEM_FINAL>>>(alpha, w_out0, b_out0, w_out1, b_out1,
                                           (float*)d_out);
}